// round 2
// baseline (speedup 1.0000x reference)
#include <cuda_runtime.h>
#include <cuda_bf16.h>

// DistortionLoss: B rays x N=128 samples.
// loss = 0.01 * mean_over_rays( (1/3)*sum s*w^2 + 2*sum_i [ wm_i*Wexcl_i - w_i*WMexcl_i ] )
// One warp per ray (grid-stride over rays); lane holds 4 consecutive elements
// (one float4 per input). Warp-scan gives exclusive prefix sums of w and w*m.

#define RAY_N 128
#define WARPS_PER_BLOCK 8
#define BLOCK_THREADS (WARPS_PER_BLOCK * 32)
#define GRID_BLOCKS 4096

__device__ float g_partials[GRID_BLOCKS];

__global__ void __launch_bounds__(BLOCK_THREADS)
distloss_kernel(const float* __restrict__ W,
                const float* __restrict__ M,
                const float* __restrict__ S,
                int B)
{
    const int lane = threadIdx.x & 31;
    const int wid  = threadIdx.x >> 5;
    const int warp_global = blockIdx.x * WARPS_PER_BLOCK + wid;
    const int warp_stride = gridDim.x * WARPS_PER_BLOCK;

    float acc = 0.0f;

    for (int ray = warp_global; ray < B; ray += warp_stride) {
        const size_t base = (size_t)ray * RAY_N;
        // lane covers elements [4*lane, 4*lane+4)
        const float4 w4 = __ldg(reinterpret_cast<const float4*>(W + base) + lane);
        const float4 m4 = __ldg(reinterpret_cast<const float4*>(M + base) + lane);
        const float4 s4 = __ldg(reinterpret_cast<const float4*>(S + base) + lane);

        float w[4]  = {w4.x, w4.y, w4.z, w4.w};
        float m[4]  = {m4.x, m4.y, m4.z, m4.w};
        float s[4]  = {s4.x, s4.y, s4.z, s4.w};
        float wm[4];
#pragma unroll
        for (int j = 0; j < 4; j++) wm[j] = w[j] * m[j];

        const float sw  = (w[0]  + w[1])  + (w[2]  + w[3]);
        const float swm = (wm[0] + wm[1]) + (wm[2] + wm[3]);

        // Warp inclusive scan of lane sums (w and wm together).
        float iw = sw, iwm = swm;
#pragma unroll
        for (int d = 1; d < 32; d <<= 1) {
            float tw  = __shfl_up_sync(0xffffffffu, iw,  d);
            float twm = __shfl_up_sync(0xffffffffu, iwm, d);
            if (lane >= d) { iw += tw; iwm += twm; }
        }
        // Exclusive prefixes at the start of this lane's 4 elements.
        float cw  = iw  - sw;
        float cwm = iwm - swm;

        float uni = 0.0f, bi = 0.0f;
#pragma unroll
        for (int j = 0; j < 4; j++) {
            uni = fmaf(s[j] * w[j], w[j], uni);
            bi  = fmaf(wm[j], cw, bi);
            bi  = fmaf(-w[j], cwm, bi);
            cw  += w[j];
            cwm += wm[j];
        }
        acc += (1.0f / 3.0f) * uni + 2.0f * bi;
    }

    // Warp reduce.
#pragma unroll
    for (int d = 16; d; d >>= 1)
        acc += __shfl_xor_sync(0xffffffffu, acc, d);

    __shared__ float sh[WARPS_PER_BLOCK];
    if (lane == 0) sh[wid] = acc;
    __syncthreads();
    if (threadIdx.x == 0) {
        float t = 0.0f;
#pragma unroll
        for (int i = 0; i < WARPS_PER_BLOCK; i++) t += sh[i];
        g_partials[blockIdx.x] = t;
    }
}

__global__ void __launch_bounds__(1024)
distloss_reduce(float* __restrict__ out, int nparts, double scale)
{
    __shared__ double sh[32];
    double acc = 0.0;
    for (int i = threadIdx.x; i < nparts; i += 1024)
        acc += (double)g_partials[i];
#pragma unroll
    for (int d = 16; d; d >>= 1)
        acc += __shfl_xor_sync(0xffffffffu, acc, d);
    const int lane = threadIdx.x & 31;
    const int wid  = threadIdx.x >> 5;
    if (lane == 0) sh[wid] = acc;
    __syncthreads();
    if (threadIdx.x == 0) {
        double t = 0.0;
#pragma unroll
        for (int i = 0; i < 32; i++) t += sh[i];
        *out = (float)(t * scale);
    }
}

extern "C" void kernel_launch(void* const* d_in, const int* in_sizes, int n_in,
                              void* d_out, int out_size)
{
    const float* W = (const float*)d_in[0];  // weights  [B, 128]
    const float* M = (const float*)d_in[1];  // distances[B, 128]
    const float* S = (const float*)d_in[2];  // intervals[B, 128]
    float* out = (float*)d_out;

    const int total = in_sizes[0];
    const int B = total / RAY_N;

    int nblocks = (B + WARPS_PER_BLOCK - 1) / WARPS_PER_BLOCK;
    if (nblocks > GRID_BLOCKS) nblocks = GRID_BLOCKS;
    if (nblocks < 1) nblocks = 1;

    distloss_kernel<<<nblocks, BLOCK_THREADS>>>(W, M, S, B);

    const double scale = 0.01 / (double)B;  // LOSS_WEIGHT / B
    distloss_reduce<<<1, 1024>>>(out, nblocks, scale);
}